// round 2
// baseline (speedup 1.0000x reference)
#include <cuda_runtime.h>

// GenLoss: combined = mean_b( masked-mean_c( MAE(out,target)[b,c] ) ) - 0.01*mean(labels)/(epoch+1)
//
// Input order (metadata): out_labels f32[16,1,30,30], out_images f32[16,3,512,512],
//                         target_images f32[16,3,512,512], epoch int32[1]
// Output: 1 float.

#define PLANES      48          // 16 batch * 3 channels
#define BPP         16          // blocks per plane
#define THREADS     256
#define PLANE_ELEMS (512*512)   // 262144
#define BLOCK_ELEMS (PLANE_ELEMS/BPP)          // 16384
#define VEC_ITERS   (BLOCK_ELEMS/(THREADS*4))  // 16

__device__ float g_psum[PLANES * BPP];
__device__ int   g_pflag[PLANES * BPP];

__global__ void __launch_bounds__(THREADS)
k_reduce(const float* __restrict__ out_img, const float* __restrict__ tgt_img)
{
    const int plane = blockIdx.x / BPP;
    const int sub   = blockIdx.x % BPP;
    const long base = (long)plane * PLANE_ELEMS + (long)sub * BLOCK_ELEMS;

    const float4* __restrict__ o = (const float4*)(out_img + base);
    const float4* __restrict__ t = (const float4*)(tgt_img + base);

    float s = 0.0f;
    int   flag = 0;
    #pragma unroll
    for (int j = 0; j < VEC_ITERS; j++) {
        float4 a = o[threadIdx.x + j * THREADS];
        float4 b = t[threadIdx.x + j * THREADS];
        s += fabsf(a.x - b.x) + fabsf(a.y - b.y)
           + fabsf(a.z - b.z) + fabsf(a.w - b.w);
        flag |= (b.x != 0.0f) | (b.y != 0.0f) | (b.z != 0.0f) | (b.w != 0.0f);
    }

    // warp reduce
    #pragma unroll
    for (int off = 16; off; off >>= 1) {
        s    += __shfl_down_sync(0xffffffffu, s, off);
        flag |= __shfl_down_sync(0xffffffffu, flag, off);
    }

    __shared__ float ss[THREADS / 32];
    __shared__ int   sf[THREADS / 32];
    const int wid = threadIdx.x >> 5;
    const int lid = threadIdx.x & 31;
    if (lid == 0) { ss[wid] = s; sf[wid] = flag; }
    __syncthreads();

    if (wid == 0) {
        s    = (lid < THREADS / 32) ? ss[lid] : 0.0f;
        flag = (lid < THREADS / 32) ? sf[lid] : 0;
        #pragma unroll
        for (int off = 16; off; off >>= 1) {
            s    += __shfl_down_sync(0xffffffffu, s, off);
            flag |= __shfl_down_sync(0xffffffffu, flag, off);
        }
        if (lid == 0) {
            g_psum[blockIdx.x]  = s;
            g_pflag[blockIdx.x] = flag;
        }
    }
}

__global__ void __launch_bounds__(THREADS)
k_final(const float* __restrict__ labels, int n_labels,
        const int* __restrict__ epoch, float* __restrict__ out)
{
    __shared__ float plane_mae[PLANES];
    __shared__ int   plane_valid[PLANES];
    __shared__ float ws[THREADS / 32];

    const int tid = threadIdx.x;

    if (tid < PLANES) {
        float s = 0.0f; int f = 0;
        #pragma unroll
        for (int i = 0; i < BPP; i++) {
            s += g_psum[tid * BPP + i];
            f |= g_pflag[tid * BPP + i];
        }
        plane_mae[tid]   = s * (1.0f / (float)PLANE_ELEMS);
        plane_valid[tid] = f;
    }

    // labels sum
    float ls = 0.0f;
    for (int i = tid; i < n_labels; i += THREADS) ls += labels[i];
    #pragma unroll
    for (int off = 16; off; off >>= 1) ls += __shfl_down_sync(0xffffffffu, ls, off);
    const int wid = tid >> 5, lid = tid & 31;
    if (lid == 0) ws[wid] = ls;
    __syncthreads();

    if (tid == 0) {
        float lsum = 0.0f;
        #pragma unroll
        for (int w = 0; w < THREADS / 32; w++) lsum += ws[w];
        const float lmean = lsum / (float)n_labels;

        float img = 0.0f;
        #pragma unroll
        for (int b = 0; b < 16; b++) {
            float tot = 0.0f, cnt = 0.0f;
            #pragma unroll
            for (int c = 0; c < 3; c++) {
                const int p = b * 3 + c;
                if (plane_valid[p]) { tot += plane_mae[p]; cnt += 1.0f; }
            }
            img += (cnt > 0.0f) ? (tot / cnt) : 0.0f;
        }
        img *= (1.0f / 16.0f);

        const float adv = -lmean;
        out[0] = img + 0.01f * adv / (float)(epoch[0] + 1);
    }
}

extern "C" void kernel_launch(void* const* d_in, const int* in_sizes, int n_in,
                              void* d_out, int out_size)
{
    const float* labels  = (const float*)d_in[0];
    const float* out_img = (const float*)d_in[1];
    const float* tgt_img = (const float*)d_in[2];
    const int*   epoch   = (const int*)d_in[3];
    float*       out     = (float*)d_out;

    k_reduce<<<PLANES * BPP, THREADS>>>(out_img, tgt_img);
    k_final<<<1, THREADS>>>(labels, in_sizes[0], epoch, out);
}